// round 12
// baseline (speedup 1.0000x reference)
#include <cuda_runtime.h>
#include <cuda_fp16.h>
#include <math.h>
#include <stdint.h>

#define BSZ 4
#define NX 8192
#define NY 1024
#define KNN 20
#define CD 24
#define HD 128
#define NB 5
#define NROWS (BSZ*NX*KNN)   /* 655360 */
#define NPTS  (BSZ*NX)       /* 32768  */
#define BN_EPS 1e-5f

typedef unsigned long long ull;

/* ---------------- f32x2 packed helpers ---------------- */
__device__ __forceinline__ ull ffma2(ull a, ull b, ull c) {
    ull d;
    asm("fma.rn.f32x2 %0, %1, %2, %3;" : "=l"(d) : "l"(a), "l"(b), "l"(c));
    return d;
}
__device__ __forceinline__ ull pack2(float lo, float hi) {
    ull d;
    asm("mov.b64 %0, {%1, %2};" : "=l"(d) : "f"(lo), "f"(hi));
    return d;
}
__device__ __forceinline__ float2 unpack2(ull v) {
    float2 r;
    asm("mov.b64 {%0, %1}, %2;" : "=f"(r.x), "=f"(r.y) : "l"(v));
    return r;
}

/* ---------------- warp mma m16n8k16 f16 -> f32 ---------------- */
__device__ __forceinline__ void mma16816(float* d, uint32_t a0, uint32_t a1,
                                         uint32_t a2, uint32_t a3,
                                         uint32_t b0, uint32_t b1) {
    asm volatile(
        "mma.sync.aligned.m16n8k16.row.col.f32.f16.f16.f32 "
        "{%0,%1,%2,%3}, {%4,%5,%6,%7}, {%8,%9}, {%0,%1,%2,%3};"
        : "+f"(d[0]), "+f"(d[1]), "+f"(d[2]), "+f"(d[3])
        : "r"(a0), "r"(a1), "r"(a2), "r"(a3), "r"(b0), "r"(b1));
}

/* ---------------- scratch ---------------- */
__device__ int    g_idx[NROWS];                 /* 2.6 MB */
__device__ float  g_U[BSZ*NY*HD];               /* 2 MB   */
__device__ float  g_V[BSZ*NX*HD];               /* 16 MB  */
__device__ __half g_h2h[(size_t)NROWS*HD];      /* 168 MB */
__device__ float  g_pmax[NPTS*CD];              /* 3 MB   */
__device__ float  g_pmin[NPTS*CD];              /* 3 MB   */
__device__ __half g_W16[HD*HD];                 /* w2^T fp16 */
__device__ float  g_sum[3*HD];
__device__ float  g_sumsq[3*HD];
__device__ float  g_scale[3*HD];
__device__ float  g_shift[3*HD];
__device__ int    g_cnt[3];

__device__ __forceinline__ void bn_finalize(int L, int C, float invN,
                                            const float* g, const float* b, int c) {
    if (c < C) {
        float mean = g_sum[L*HD + c] * invN;
        float var  = g_sumsq[L*HD + c] * invN - mean*mean;
        float sc = g[c] * rsqrtf(var + BN_EPS);
        g_scale[L*HD + c] = sc;
        g_shift[L*HD + c] = b[c] - mean*sc;
    }
}

/* ---------------- K1: KNN (+ zero stats/counters in block 0) ---------------- */
__global__ void k_knn(const float* __restrict__ p, const float* __restrict__ pc) {
    __shared__ float qx[NY], qy[NY], qz[NY], qn[NY];
    int b = blockIdx.y;
    int t = threadIdx.x;
    if (blockIdx.x == 0 && blockIdx.y == 0) {
        for (int c = t; c < 3*HD; c += 256) { g_sum[c] = 0.f; g_sumsq[c] = 0.f; }
        if (t < 3) g_cnt[t] = 0;
    }
    for (int j = t; j < NY; j += blockDim.x) {
        float x = pc[(b*NY + j)*3 + 0];
        float y = pc[(b*NY + j)*3 + 1];
        float z = pc[(b*NY + j)*3 + 2];
        qx[j] = x; qy[j] = y; qz[j] = z;
        qn[j] = x*x + y*y + z*z;
    }
    __syncthreads();

    int n = blockIdx.x * blockDim.x + t;
    float px = p[(b*NX + n)*3 + 0];
    float py = p[(b*NX + n)*3 + 1];
    float pz = p[(b*NX + n)*3 + 2];
    float pn = px*px + py*py + pz*pz;

    float bd[KNN]; int bi[KNN];
#pragma unroll
    for (int s = 0; s < KNN; s++) { bd[s] = 3.4e38f; bi[s] = 0; }
    float worst = 3.4e38f; int wpos = 0;

    for (int j = 0; j < NY; j++) {
        float d = pn + qn[j] - 2.f*(px*qx[j] + py*qy[j] + pz*qz[j]);
        if (d < worst) {
#pragma unroll
            for (int s = 0; s < KNN; s++) if (s == wpos) { bd[s] = d; bi[s] = j; }
            worst = bd[0]; wpos = 0;
#pragma unroll
            for (int s = 1; s < KNN; s++) if (bd[s] > worst) { worst = bd[s]; wpos = s; }
        }
    }
    int base = (b*NX + n)*KNN;
#pragma unroll
    for (int s = 0; s < KNN; s++) g_idx[base + s] = bi[s];
}

/* ---------------- K2: fused preU + preV + prepW (verified in R8 pass) ------- */
__global__ void k_preUVW(const float* __restrict__ p, const float* __restrict__ pc,
                         const float* __restrict__ feat, const float* __restrict__ w1,
                         const float* __restrict__ w2) {
    int t = threadIdx.x;
    if (blockIdx.x < 128) {
        __shared__ float in_s[32][28];
        int base = blockIdx.x * 32;
        for (int e = t; e < 32*27; e += 128) {
            int r = e / 27, k = e % 27;
            int row = base + r;
            in_s[r][k] = (k < 3) ? pc[row*3 + k] : feat[row*24 + (k - 3)];
        }
        __syncthreads();
        float wr[27];
#pragma unroll
        for (int d = 0; d < 3; d++)  wr[d]     = w1[d*HD + t];
#pragma unroll
        for (int k = 0; k < 24; k++) wr[3 + k] = w1[(6 + k)*HD + t];
        for (int r = 0; r < 32; r++) {
            float acc = 0.f;
#pragma unroll
            for (int k = 0; k < 27; k++) acc = fmaf(in_s[r][k], wr[k], acc);
            g_U[(base + r)*HD + t] = acc;
        }
    } else if (blockIdx.x < 640) {
        __shared__ float ps[64][4];
        int base = (blockIdx.x - 128) * 64;
        for (int e = t; e < 64*3; e += 128) {
            int r = e / 3, d = e % 3;
            ps[r][d] = p[(base + r)*3 + d];
        }
        __syncthreads();
        float wd0 = w1[3*HD + t] - w1[0*HD + t];
        float wd1 = w1[4*HD + t] - w1[1*HD + t];
        float wd2 = w1[5*HD + t] - w1[2*HD + t];
        for (int r = 0; r < 64; r++) {
            float v = fmaf(ps[r][0], wd0, fmaf(ps[r][1], wd1, ps[r][2]*wd2));
            g_V[(base + r)*HD + t] = v;
        }
    } else {
        int e = (blockIdx.x - 640) * 128 + t;
        int n = e >> 7, k = e & 127;
        g_W16[e] = __float2half(w2[k*HD + n]);
    }
}

/* ---------------- K3: stats of h1 + fused finalize layer 0 ---------------- */
__global__ void k_stats1(const float* __restrict__ bn1g, const float* __restrict__ bn1b,
                         float invN) {
    __shared__ int uo[512], vo[512];
    __shared__ int lastflag;
    int blk = blockIdx.x, t = threadIdx.x;
    int base = blk * 512;
    for (int r = t; r < 512; r += 256) {
        int grow = base + r;
        int j = g_idx[grow];
        int b = grow / (NX*KNN);
        int n = (grow / KNN) % NX;
        uo[r] = (b*NY + j)*HD;
        vo[r] = (b*NX + n)*HD;
    }
    __syncthreads();
    int c = t & 127, rg = t >> 7;
    float s = 0.f, s2 = 0.f;
    for (int r = rg; r < 512; r += 2) {
        float v = g_U[uo[r] + c] + g_V[vo[r] + c];
        s += v; s2 += v*v;
    }
    atomicAdd(&g_sum[c], s);
    atomicAdd(&g_sumsq[c], s2);
    __threadfence();
    __syncthreads();   /* race fix: all threads' atomics precede counter arrival */
    if (t == 0) lastflag = (atomicAdd(&g_cnt[0], 1) == (int)gridDim.x - 1);
    __syncthreads();
    if (lastflag) bn_finalize(0, 128, invN, bn1g, bn1b, t);
}

/* ---------------- K4: conv2 via warp mma (R8-verified) ---------------- */
#define C2_PH 136
#define C2_PW 68
#define C2_AS 2048
#define C2_BS (2048 + 34816)
#define C2_SMEM (2048 + 2*34816)
__global__ void __launch_bounds__(256) k_conv2(const float* __restrict__ bn2g,
                                               const float* __restrict__ bn2b,
                                               float invN) {
    extern __shared__ char smemraw[];
    float* sc = (float*)smemraw;
    float* sh = sc + 128;
    int*   uo = (int*)(sh + 128);
    int*   vo = uo + 128;
    __shared__ int lastflag;

    int t = threadIdx.x, blk = blockIdx.x;
    int lane = t & 31, wid = t >> 5;
    int rbase = blk * 128;
    __half* As = (__half*)(smemraw + C2_AS);
    __half* Bs = (__half*)(smemraw + C2_BS);

    if (t < 128) {
        int grow = rbase + t;
        int j = g_idx[grow];
        int b = grow / (NX*KNN);
        int n = (grow / KNN) % NX;
        uo[t] = (b*NY + j)*HD;
        vo[t] = (b*NX + n)*HD;
    } else {
        int c = t - 128;
        sc[c] = g_scale[c];
        sh[c] = g_shift[c];
    }
    __syncthreads();

    for (int e = t; e < HD*HD; e += 256) {
        int n = e >> 7, k = e & 127;
        Bs[n*C2_PH + k] = g_W16[e];
    }
    {
        int k = t & 127;
        for (int r = (t >> 7); r < 128; r += 2) {
            float v = g_U[uo[r] + k] + g_V[vo[r] + k];
            v = fmaf(sc[k], v, sh[k]);
            v = (v > 0.f) ? v : 0.2f*v;
            As[r*C2_PH + k] = __float2half(v);
        }
    }
    __syncthreads();

    const uint32_t* As32 = (const uint32_t*)As;
    const uint32_t* Bs32 = (const uint32_t*)Bs;
    int gid = lane >> 2, tid = lane & 3;
    int ar0 = wid*16 + gid;
    float d[16][4];
#pragma unroll
    for (int nb = 0; nb < 16; nb++)
#pragma unroll
        for (int j = 0; j < 4; j++) d[nb][j] = 0.f;

#pragma unroll
    for (int k0 = 0; k0 < 8; k0++) {
        int kc = k0*8 + tid;
        uint32_t a0 = As32[ar0*C2_PW + kc];
        uint32_t a1 = As32[(ar0+8)*C2_PW + kc];
        uint32_t a2 = As32[ar0*C2_PW + kc + 4];
        uint32_t a3 = As32[(ar0+8)*C2_PW + kc + 4];
#pragma unroll
        for (int nb = 0; nb < 16; nb++) {
            uint32_t b0 = Bs32[(nb*8+gid)*C2_PW + kc];
            uint32_t b1 = Bs32[(nb*8+gid)*C2_PW + kc + 4];
            mma16816(d[nb], a0, a1, a2, a3, b0, b1);
        }
    }
    __syncthreads();

    __half2* hst2 = (__half2*)(smemraw + C2_AS);
#pragma unroll
    for (int nb = 0; nb < 16; nb++) {
        hst2[ar0*C2_PW + nb*4 + tid]     = __floats2half2_rn(d[nb][0], d[nb][1]);
        hst2[(ar0+8)*C2_PW + nb*4 + tid] = __floats2half2_rn(d[nb][2], d[nb][3]);
    }
    __syncthreads();
    {
        __half2* dst = (__half2*)&g_h2h[(size_t)rbase*HD];
        for (int e = t; e < 128*64; e += 256) {
            int r = e >> 6, j = e & 63;
            dst[e] = hst2[r*C2_PW + j];
        }
    }
    {
        int c2 = t & 63, rg = t >> 6;
        float s0 = 0.f, q0 = 0.f, s1 = 0.f, q1 = 0.f;
        for (int r = rg*32; r < rg*32 + 32; r++) {
            float2 f = __half22float2(hst2[r*C2_PW + c2]);
            s0 += f.x; q0 += f.x*f.x;
            s1 += f.y; q1 += f.y*f.y;
        }
        atomicAdd(&g_sum[HD + 2*c2],     s0);
        atomicAdd(&g_sumsq[HD + 2*c2],   q0);
        atomicAdd(&g_sum[HD + 2*c2+1],   s1);
        atomicAdd(&g_sumsq[HD + 2*c2+1], q1);
    }
    __threadfence();
    __syncthreads();   /* race fix */
    if (t == 0) lastflag = (atomicAdd(&g_cnt[1], 1) == (int)gridDim.x - 1);
    __syncthreads();
    if (lastflag) bn_finalize(1, 128, invN, bn2g, bn2b, t);
}

/* ---------------- K5: conv3 GEMM (f32x2, R8-verified) + fused pool ---------- */
__global__ void __launch_bounds__(192) k_conv3p(const float* __restrict__ w3,
                                                const float* __restrict__ bn3g,
                                                const float* __restrict__ bn3b,
                                                float invN) {
    extern __shared__ char smemraw[];
    float* a_s = (float*)smemraw;          /* 160*130 */
    ull*   wp  = (ull*)(a_s + 160*130);    /* 64*24 u64 */
    float* sc  = (float*)(wp + 64*24);
    float* sh  = sc + 128;
    float* red = sh + 128;
    __shared__ int lastflag;

    int t = threadIdx.x, blk = blockIdx.x;
    int rbase = blk * 160;
    for (int e = t; e < 64*24; e += 192) {
        int pp = e / 24, col = e % 24;
        wp[e] = pack2(__ldg(&w3[(2*pp)*24 + col]), __ldg(&w3[(2*pp+1)*24 + col]));
    }
    if (t < 128) { sc[t] = g_scale[HD + t]; sh[t] = g_shift[HD + t]; }
    if (t < 48)  red[t] = 0.f;
    __syncthreads();

    const __half2* hp = (const __half2*)g_h2h + (size_t)rbase*64;
    for (int e = t; e < 160*64; e += 192) {
        int r = e >> 6, kp = e & 63;
        float2 f = __half22float2(hp[(size_t)r*64 + kp]);
        int k0 = 2*kp;
        float v0 = fmaf(sc[k0],   f.x, sh[k0]);   v0 = (v0 > 0.f) ? v0 : 0.2f*v0;
        float v1 = fmaf(sc[k0+1], f.y, sh[k0+1]); v1 = (v1 > 0.f) ? v1 : 0.2f*v1;
        a_s[r*130 + k0]     = v0;
        a_s[r*130 + k0 + 1] = v1;
    }
    __syncthreads();

    int col = t % 24, rg = t / 24;
    ull acc2[20];
#pragma unroll
    for (int r = 0; r < 20; r++) acc2[r] = 0ULL;
#pragma unroll 2
    for (int p = 0; p < 64; p++) {
        ull wv = wp[p*24 + col];
#pragma unroll
        for (int r = 0; r < 20; r++) {
            ull a = *(const ull*)&a_s[(r*8 + rg)*130 + 2*p];
            acc2[r] = ffma2(a, wv, acc2[r]);
        }
    }
    __syncthreads();
    float* h3s = a_s;
    float s = 0.f, s2 = 0.f;
#pragma unroll
    for (int r = 0; r < 20; r++) {
        float2 f = unpack2(acc2[r]);
        float v = f.x + f.y;
        h3s[(r*8 + rg)*24 + col] = v;
        s += v; s2 += v*v;
    }
    atomicAdd(&red[col], s);
    atomicAdd(&red[24 + col], s2);
    __syncthreads();

    {
        int pl = t / 24, c2 = t % 24;
        float mx = -3.4e38f, mn = 3.4e38f;
#pragma unroll
        for (int kk = 0; kk < KNN; kk++) {
            float v = h3s[(pl*KNN + kk)*24 + c2];
            mx = fmaxf(mx, v); mn = fminf(mn, v);
        }
        int pt = blk*8 + pl;
        g_pmax[pt*24 + c2] = mx;
        g_pmin[pt*24 + c2] = mn;
    }
    if (t < 24) {
        atomicAdd(&g_sum[2*HD + t],   red[t]);
        atomicAdd(&g_sumsq[2*HD + t], red[24 + t]);
    }
    __threadfence();
    __syncthreads();   /* race fix */
    if (t == 0) lastflag = (atomicAdd(&g_cnt[2], 1) == (int)gridDim.x - 1);
    __syncthreads();
    if (lastflag) bn_finalize(2, 24, invN, bn3g, bn3b, t);
}

/* ---------------- K6: ResNet-FC head (f32x2, R8-verified) ---------------- */
__global__ void __launch_bounds__(256) k_head(const float* __restrict__ p,
                       const float* __restrict__ fpw, const float* __restrict__ fpb,
                       const float* __restrict__ fcw, const float* __restrict__ fcb,
                       const float* __restrict__ b0w, const float* __restrict__ b0b,
                       const float* __restrict__ b1w, const float* __restrict__ b1b,
                       const float* __restrict__ fow, const float* __restrict__ fob,
                       float* __restrict__ out) {
    extern __shared__ char smemraw[];
    float* net  = (float*)smemraw;
    float* rnet = net  + 64*128;
    float* rhh  = rnet + 64*128;
    float* cb   = rhh  + 64*128;
    float* pb   = cb   + 64*24;
    float* fo   = pb   + 192;

    int t = threadIdx.x;
    int base = blockIdx.x * 64;
    for (int e = t; e < 64*CD; e += 256) {
        int c2 = e % 24;
        float scv = g_scale[2*HD + c2], shv = g_shift[2*HD + c2];
        float v = (scv >= 0.f) ? g_pmax[base*24 + e] : g_pmin[base*24 + e];
        v = fmaf(scv, v, shv);
        cb[e] = (v > 0.f) ? v : 0.2f*v;
    }
    if (t < 192) pb[t] = p[base*3 + t];
    if (t < 128) fo[t] = fow[t];
    __syncthreads();

    int cg  = (t & 31) * 4;
    int row0 = (t >> 5) * 8;

    {
        float4 w0 = *(const float4*)&fpw[0*HD + cg];
        float4 w1 = *(const float4*)&fpw[1*HD + cg];
        float4 w2 = *(const float4*)&fpw[2*HD + cg];
        float4 b4 = *(const float4*)&fpb[cg];
#pragma unroll
        for (int rr = 0; rr < 8; rr++) {
            int row = row0 + rr;
            float p0 = pb[row*3+0], p1 = pb[row*3+1], p2 = pb[row*3+2];
            float4 v;
            v.x = fmaf(p0,w0.x, fmaf(p1,w1.x, fmaf(p2,w2.x, b4.x)));
            v.y = fmaf(p0,w0.y, fmaf(p1,w1.y, fmaf(p2,w2.y, b4.y)));
            v.z = fmaf(p0,w0.z, fmaf(p1,w1.z, fmaf(p2,w2.z, b4.z)));
            v.w = fmaf(p0,w0.w, fmaf(p1,w1.w, fmaf(p2,w2.w, b4.w)));
            *(float4*)&net[row*128 + cg] = v;
        }
    }
    __syncthreads();

    for (int i = 0; i < NB; i++) {
        {
            float4 b4 = *(const float4*)&fcb[i*HD + cg];
            ull acc2[8][4];
#pragma unroll
            for (int rr = 0; rr < 8; rr++) {
                float4 v = *(const float4*)&net[(row0+rr)*128 + cg];
                acc2[rr][0] = pack2(v.x + b4.x, 0.f);
                acc2[rr][1] = pack2(v.y + b4.y, 0.f);
                acc2[rr][2] = pack2(v.z + b4.z, 0.f);
                acc2[rr][3] = pack2(v.w + b4.w, 0.f);
            }
#pragma unroll 2
            for (int k = 0; k < CD; k += 2) {
                float4 wa = __ldg((const float4*)&fcw[(i*CD + k)*HD + cg]);
                float4 wb = __ldg((const float4*)&fcw[(i*CD + k + 1)*HD + cg]);
                ull wx = pack2(wa.x, wb.x), wy = pack2(wa.y, wb.y);
                ull wz = pack2(wa.z, wb.z), ww = pack2(wa.w, wb.w);
#pragma unroll
                for (int rr = 0; rr < 8; rr++) {
                    ull a = *(const ull*)&cb[(row0+rr)*24 + k];
                    acc2[rr][0] = ffma2(a, wx, acc2[rr][0]);
                    acc2[rr][1] = ffma2(a, wy, acc2[rr][1]);
                    acc2[rr][2] = ffma2(a, wz, acc2[rr][2]);
                    acc2[rr][3] = ffma2(a, ww, acc2[rr][3]);
                }
            }
#pragma unroll
            for (int rr = 0; rr < 8; rr++) {
                int row = row0 + rr;
                float2 f0 = unpack2(acc2[rr][0]), f1 = unpack2(acc2[rr][1]);
                float2 f2 = unpack2(acc2[rr][2]), f3 = unpack2(acc2[rr][3]);
                float4 v; v.x = f0.x+f0.y; v.y = f1.x+f1.y; v.z = f2.x+f2.y; v.w = f3.x+f3.y;
                *(float4*)&net[row*128 + cg] = v;
                float4 rv;
                rv.x = fmaxf(v.x, 0.f); rv.y = fmaxf(v.y, 0.f);
                rv.z = fmaxf(v.z, 0.f); rv.w = fmaxf(v.w, 0.f);
                *(float4*)&rnet[row*128 + cg] = rv;
            }
        }
        __syncthreads();
        {
            float4 b4 = *(const float4*)&b0b[i*HD + cg];
            ull acc2[8][4];
#pragma unroll
            for (int rr = 0; rr < 8; rr++) {
                acc2[rr][0] = pack2(b4.x, 0.f); acc2[rr][1] = pack2(b4.y, 0.f);
                acc2[rr][2] = pack2(b4.z, 0.f); acc2[rr][3] = pack2(b4.w, 0.f);
            }
            const float* wbase = b0w + (size_t)i*HD*HD;
#pragma unroll 2
            for (int k = 0; k < HD; k += 2) {
                float4 wa = __ldg((const float4*)&wbase[k*HD + cg]);
                float4 wb = __ldg((const float4*)&wbase[(k+1)*HD + cg]);
                ull wx = pack2(wa.x, wb.x), wy = pack2(wa.y, wb.y);
                ull wz = pack2(wa.z, wb.z), ww = pack2(wa.w, wb.w);
#pragma unroll
                for (int rr = 0; rr < 8; rr++) {
                    ull a = *(const ull*)&rnet[(row0+rr)*128 + k];
                    acc2[rr][0] = ffma2(a, wx, acc2[rr][0]);
                    acc2[rr][1] = ffma2(a, wy, acc2[rr][1]);
                    acc2[rr][2] = ffma2(a, wz, acc2[rr][2]);
                    acc2[rr][3] = ffma2(a, ww, acc2[rr][3]);
                }
            }
#pragma unroll
            for (int rr = 0; rr < 8; rr++) {
                float2 f0 = unpack2(acc2[rr][0]), f1 = unpack2(acc2[rr][1]);
                float2 f2 = unpack2(acc2[rr][2]), f3 = unpack2(acc2[rr][3]);
                float4 rv;
                rv.x = fmaxf(f0.x+f0.y, 0.f); rv.y = fmaxf(f1.x+f1.y, 0.f);
                rv.z = fmaxf(f2.x+f2.y, 0.f); rv.w = fmaxf(f3.x+f3.y, 0.f);
                *(float4*)&rhh[(row0+rr)*128 + cg] = rv;
            }
        }
        __syncthreads();
        {
            float4 b4 = *(const float4*)&b1b[i*HD + cg];
            ull acc2[8][4];
#pragma unroll
            for (int rr = 0; rr < 8; rr++) {
                acc2[rr][0] = pack2(b4.x, 0.f); acc2[rr][1] = pack2(b4.y, 0.f);
                acc2[rr][2] = pack2(b4.z, 0.f); acc2[rr][3] = pack2(b4.w, 0.f);
            }
            const float* wbase = b1w + (size_t)i*HD*HD;
#pragma unroll 2
            for (int k = 0; k < HD; k += 2) {
                float4 wa = __ldg((const float4*)&wbase[k*HD + cg]);
                float4 wb = __ldg((const float4*)&wbase[(k+1)*HD + cg]);
                ull wx = pack2(wa.x, wb.x), wy = pack2(wa.y, wb.y);
                ull wz = pack2(wa.z, wb.z), ww = pack2(wa.w, wb.w);
#pragma unroll
                for (int rr = 0; rr < 8; rr++) {
                    ull a = *(const ull*)&rhh[(row0+rr)*128 + k];
                    acc2[rr][0] = ffma2(a, wx, acc2[rr][0]);
                    acc2[rr][1] = ffma2(a, wy, acc2[rr][1]);
                    acc2[rr][2] = ffma2(a, wz, acc2[rr][2]);
                    acc2[rr][3] = ffma2(a, ww, acc2[rr][3]);
                }
            }
#pragma unroll
            for (int rr = 0; rr < 8; rr++) {
                int row = row0 + rr;
                float2 f0 = unpack2(acc2[rr][0]), f1 = unpack2(acc2[rr][1]);
                float2 f2 = unpack2(acc2[rr][2]), f3 = unpack2(acc2[rr][3]);
                float4 v = *(const float4*)&net[row*128 + cg];
                v.x += f0.x+f0.y; v.y += f1.x+f1.y;
                v.z += f2.x+f2.y; v.w += f3.x+f3.y;
                *(float4*)&net[row*128 + cg] = v;
            }
        }
        __syncthreads();
    }

    if (t < 64) {
        float s = fob[0];
        for (int c2 = 0; c2 < HD; c2++)
            s = fmaf(fmaxf(net[t*128 + c2], 0.f), fo[c2], s);
        out[base + t] = s;
    }
}

/* ---------------- launch ---------------- */
extern "C" void kernel_launch(void* const* d_in, const int* in_sizes, int n_in,
                              void* d_out, int out_size) {
    (void)in_sizes; (void)n_in; (void)out_size;
    const float* p     = (const float*)d_in[0];
    const float* pc    = (const float*)d_in[1];
    const float* feat  = (const float*)d_in[2];
    const float* w1    = (const float*)d_in[3];
    const float* bn1g  = (const float*)d_in[4];
    const float* bn1b  = (const float*)d_in[5];
    const float* w2    = (const float*)d_in[6];
    const float* bn2g  = (const float*)d_in[7];
    const float* bn2b  = (const float*)d_in[8];
    const float* w3    = (const float*)d_in[9];
    const float* bn3g  = (const float*)d_in[10];
    const float* bn3b  = (const float*)d_in[11];
    const float* fpw   = (const float*)d_in[12];
    const float* fpb   = (const float*)d_in[13];
    const float* fcw   = (const float*)d_in[14];
    const float* fcb   = (const float*)d_in[15];
    const float* b0w   = (const float*)d_in[16];
    const float* b0b   = (const float*)d_in[17];
    const float* b1w   = (const float*)d_in[18];
    const float* b1b   = (const float*)d_in[19];
    const float* fow   = (const float*)d_in[20];
    const float* fob   = (const float*)d_in[21];
    float* out = (float*)d_out;

    const int SMEM3 = 160*130*4 + 64*24*8 + 2*128*4 + 48*4;   /* ~96.7 KB */
    const int SMEMH = (3*64*128 + 64*24 + 192 + 128) * 4;     /* ~105.7 KB */
    cudaFuncSetAttribute(k_conv2,  cudaFuncAttributeMaxDynamicSharedMemorySize, C2_SMEM);
    cudaFuncSetAttribute(k_conv3p, cudaFuncAttributeMaxDynamicSharedMemorySize, SMEM3);
    cudaFuncSetAttribute(k_head,   cudaFuncAttributeMaxDynamicSharedMemorySize, SMEMH);

    float invN = 1.0f / (float)NROWS;

    k_knn<<<dim3(NX/256, BSZ), 256>>>(p, pc);
    k_preUVW<<<768, 128>>>(p, pc, feat, w1, w2);
    k_stats1<<<NROWS/512, 256>>>(bn1g, bn1b, invN);
    k_conv2<<<NROWS/128, 256, C2_SMEM>>>(bn2g, bn2b, invN);
    k_conv3p<<<NROWS/160, 192, SMEM3>>>(w3, bn3g, bn3b, invN);
    k_head<<<NPTS/64, 256, SMEMH>>>(p, fpw, fpb, fcw, fcb,
                                    b0w, b0b, b1w, b1b, fow, fob, out);
}

// round 14
// speedup vs baseline: 1.0328x; 1.0328x over previous
#include <cuda_runtime.h>
#include <cuda_fp16.h>
#include <math.h>
#include <stdint.h>

#define BSZ 4
#define NX 8192
#define NY 1024
#define KNN 20
#define CD 24
#define HD 128
#define NB 5
#define NROWS (BSZ*NX*KNN)   /* 655360 */
#define NPTS  (BSZ*NX)       /* 32768  */
#define BN_EPS 1e-5f

typedef unsigned long long ull;

/* ---------------- f32x2 packed helpers ---------------- */
__device__ __forceinline__ ull ffma2(ull a, ull b, ull c) {
    ull d;
    asm("fma.rn.f32x2 %0, %1, %2, %3;" : "=l"(d) : "l"(a), "l"(b), "l"(c));
    return d;
}
__device__ __forceinline__ ull pack2(float lo, float hi) {
    ull d;
    asm("mov.b64 %0, {%1, %2};" : "=l"(d) : "f"(lo), "f"(hi));
    return d;
}
__device__ __forceinline__ float2 unpack2(ull v) {
    float2 r;
    asm("mov.b64 {%0, %1}, %2;" : "=f"(r.x), "=f"(r.y) : "l"(v));
    return r;
}

/* ---------------- warp mma m16n8k16 f16 -> f32 ---------------- */
__device__ __forceinline__ void mma16816(float* d, uint32_t a0, uint32_t a1,
                                         uint32_t a2, uint32_t a3,
                                         uint32_t b0, uint32_t b1) {
    asm volatile(
        "mma.sync.aligned.m16n8k16.row.col.f32.f16.f16.f32 "
        "{%0,%1,%2,%3}, {%4,%5,%6,%7}, {%8,%9}, {%0,%1,%2,%3};"
        : "+f"(d[0]), "+f"(d[1]), "+f"(d[2]), "+f"(d[3])
        : "r"(a0), "r"(a1), "r"(a2), "r"(a3), "r"(b0), "r"(b1));
}

/* ---------------- scratch ---------------- */
__device__ int    g_idx[NROWS];                 /* 2.6 MB */
__device__ float  g_U[BSZ*NY*HD];               /* 2 MB   */
__device__ float  g_V[BSZ*NX*HD];               /* 16 MB  */
__device__ __half g_h2h[(size_t)NROWS*HD];      /* 168 MB */
__device__ float  g_pmax[NPTS*CD];              /* 3 MB   */
__device__ float  g_pmin[NPTS*CD];              /* 3 MB   */
__device__ __half g_W16[HD*HD];                 /* w2^T fp16 */
__device__ float  g_sum[3*HD];
__device__ float  g_sumsq[3*HD];
__device__ float  g_scale[3*HD];
__device__ float  g_shift[3*HD];
__device__ int    g_cnt[3];

__device__ __forceinline__ void bn_finalize(int L, int C, float invN,
                                            const float* g, const float* b, int c) {
    if (c < C) {
        float mean = g_sum[L*HD + c] * invN;
        float var  = g_sumsq[L*HD + c] * invN - mean*mean;
        float sc = g[c] * rsqrtf(var + BN_EPS);
        g_scale[L*HD + c] = sc;
        g_shift[L*HD + c] = b[c] - mean*sc;
    }
}

/* ---------------- K1: KNN (+ zero stats/counters in block 0) ---------------- */
__global__ void k_knn(const float* __restrict__ p, const float* __restrict__ pc) {
    __shared__ float qx[NY], qy[NY], qz[NY], qn[NY];
    int b = blockIdx.y;
    int t = threadIdx.x;
    if (blockIdx.x == 0 && blockIdx.y == 0) {
        for (int c = t; c < 3*HD; c += 256) { g_sum[c] = 0.f; g_sumsq[c] = 0.f; }
        if (t < 3) g_cnt[t] = 0;
    }
    for (int j = t; j < NY; j += blockDim.x) {
        float x = pc[(b*NY + j)*3 + 0];
        float y = pc[(b*NY + j)*3 + 1];
        float z = pc[(b*NY + j)*3 + 2];
        qx[j] = x; qy[j] = y; qz[j] = z;
        qn[j] = x*x + y*y + z*z;
    }
    __syncthreads();

    int n = blockIdx.x * blockDim.x + t;
    float px = p[(b*NX + n)*3 + 0];
    float py = p[(b*NX + n)*3 + 1];
    float pz = p[(b*NX + n)*3 + 2];
    float pn = px*px + py*py + pz*pz;

    float bd[KNN]; int bi[KNN];
#pragma unroll
    for (int s = 0; s < KNN; s++) { bd[s] = 3.4e38f; bi[s] = 0; }
    float worst = 3.4e38f; int wpos = 0;

    for (int j = 0; j < NY; j++) {
        float d = pn + qn[j] - 2.f*(px*qx[j] + py*qy[j] + pz*qz[j]);
        if (d < worst) {
#pragma unroll
            for (int s = 0; s < KNN; s++) if (s == wpos) { bd[s] = d; bi[s] = j; }
            worst = bd[0]; wpos = 0;
#pragma unroll
            for (int s = 1; s < KNN; s++) if (bd[s] > worst) { worst = bd[s]; wpos = s; }
        }
    }
    int base = (b*NX + n)*KNN;
#pragma unroll
    for (int s = 0; s < KNN; s++) g_idx[base + s] = bi[s];
}

/* ---------------- K2: fused preU + preV + prepW ---------------- */
__global__ void k_preUVW(const float* __restrict__ p, const float* __restrict__ pc,
                         const float* __restrict__ feat, const float* __restrict__ w1,
                         const float* __restrict__ w2) {
    int t = threadIdx.x;
    if (blockIdx.x < 128) {
        __shared__ float in_s[32][28];
        int base = blockIdx.x * 32;
        for (int e = t; e < 32*27; e += 128) {
            int r = e / 27, k = e % 27;
            int row = base + r;
            in_s[r][k] = (k < 3) ? pc[row*3 + k] : feat[row*24 + (k - 3)];
        }
        __syncthreads();
        float wr[27];
#pragma unroll
        for (int d = 0; d < 3; d++)  wr[d]     = w1[d*HD + t];
#pragma unroll
        for (int k = 0; k < 24; k++) wr[3 + k] = w1[(6 + k)*HD + t];
        for (int r = 0; r < 32; r++) {
            float acc = 0.f;
#pragma unroll
            for (int k = 0; k < 27; k++) acc = fmaf(in_s[r][k], wr[k], acc);
            g_U[(base + r)*HD + t] = acc;
        }
    } else if (blockIdx.x < 640) {
        __shared__ float ps[64][4];
        int base = (blockIdx.x - 128) * 64;
        for (int e = t; e < 64*3; e += 128) {
            int r = e / 3, d = e % 3;
            ps[r][d] = p[(base + r)*3 + d];
        }
        __syncthreads();
        float wd0 = w1[3*HD + t] - w1[0*HD + t];
        float wd1 = w1[4*HD + t] - w1[1*HD + t];
        float wd2 = w1[5*HD + t] - w1[2*HD + t];
        for (int r = 0; r < 64; r++) {
            float v = fmaf(ps[r][0], wd0, fmaf(ps[r][1], wd1, ps[r][2]*wd2));
            g_V[(base + r)*HD + t] = v;
        }
    } else {
        int e = (blockIdx.x - 640) * 128 + t;
        int n = e >> 7, k = e & 127;
        g_W16[e] = __float2half(w2[k*HD + n]);
    }
}

/* ---------------- K3: stats of h1 + fused finalize layer 0 ---------------- */
__global__ void k_stats1(const float* __restrict__ bn1g, const float* __restrict__ bn1b,
                         float invN) {
    __shared__ int uo[512], vo[512];
    __shared__ int lastflag;
    int blk = blockIdx.x, t = threadIdx.x;
    int base = blk * 512;
    for (int r = t; r < 512; r += 256) {
        int grow = base + r;
        int j = g_idx[grow];
        int b = grow / (NX*KNN);
        int n = (grow / KNN) % NX;
        uo[r] = (b*NY + j)*HD;
        vo[r] = (b*NX + n)*HD;
    }
    __syncthreads();
    int c = t & 127, rg = t >> 7;
    float s = 0.f, s2 = 0.f;
    for (int r = rg; r < 512; r += 2) {
        float v = g_U[uo[r] + c] + g_V[vo[r] + c];
        s += v; s2 += v*v;
    }
    atomicAdd(&g_sum[c], s);
    atomicAdd(&g_sumsq[c], s2);
    __threadfence();
    __syncthreads();
    if (t == 0) lastflag = (atomicAdd(&g_cnt[0], 1) == (int)gridDim.x - 1);
    __syncthreads();
    if (lastflag) bn_finalize(0, 128, invN, bn1g, bn1b, t);
}

/* ---------------- K4: conv2 via warp mma (R8-verified) ---------------- */
#define C2_PH 136
#define C2_PW 68
#define C2_AS 2048
#define C2_BS (2048 + 34816)
#define C2_SMEM (2048 + 2*34816)
__global__ void __launch_bounds__(256) k_conv2(const float* __restrict__ bn2g,
                                               const float* __restrict__ bn2b,
                                               float invN) {
    extern __shared__ char smemraw[];
    float* sc = (float*)smemraw;
    float* sh = sc + 128;
    int*   uo = (int*)(sh + 128);
    int*   vo = uo + 128;
    __shared__ int lastflag;

    int t = threadIdx.x, blk = blockIdx.x;
    int lane = t & 31, wid = t >> 5;
    int rbase = blk * 128;
    __half* As = (__half*)(smemraw + C2_AS);
    __half* Bs = (__half*)(smemraw + C2_BS);

    if (t < 128) {
        int grow = rbase + t;
        int j = g_idx[grow];
        int b = grow / (NX*KNN);
        int n = (grow / KNN) % NX;
        uo[t] = (b*NY + j)*HD;
        vo[t] = (b*NX + n)*HD;
    } else {
        int c = t - 128;
        sc[c] = g_scale[c];
        sh[c] = g_shift[c];
    }
    __syncthreads();

    for (int e = t; e < HD*HD; e += 256) {
        int n = e >> 7, k = e & 127;
        Bs[n*C2_PH + k] = g_W16[e];
    }
    {
        int k = t & 127;
        for (int r = (t >> 7); r < 128; r += 2) {
            float v = g_U[uo[r] + k] + g_V[vo[r] + k];
            v = fmaf(sc[k], v, sh[k]);
            v = (v > 0.f) ? v : 0.2f*v;
            As[r*C2_PH + k] = __float2half(v);
        }
    }
    __syncthreads();

    const uint32_t* As32 = (const uint32_t*)As;
    const uint32_t* Bs32 = (const uint32_t*)Bs;
    int gid = lane >> 2, tid = lane & 3;
    int ar0 = wid*16 + gid;
    float d[16][4];
#pragma unroll
    for (int nb = 0; nb < 16; nb++)
#pragma unroll
        for (int j = 0; j < 4; j++) d[nb][j] = 0.f;

#pragma unroll
    for (int k0 = 0; k0 < 8; k0++) {
        int kc = k0*8 + tid;
        uint32_t a0 = As32[ar0*C2_PW + kc];
        uint32_t a1 = As32[(ar0+8)*C2_PW + kc];
        uint32_t a2 = As32[ar0*C2_PW + kc + 4];
        uint32_t a3 = As32[(ar0+8)*C2_PW + kc + 4];
#pragma unroll
        for (int nb = 0; nb < 16; nb++) {
            uint32_t b0 = Bs32[(nb*8+gid)*C2_PW + kc];
            uint32_t b1 = Bs32[(nb*8+gid)*C2_PW + kc + 4];
            mma16816(d[nb], a0, a1, a2, a3, b0, b1);
        }
    }
    __syncthreads();

    __half2* hst2 = (__half2*)(smemraw + C2_AS);
#pragma unroll
    for (int nb = 0; nb < 16; nb++) {
        hst2[ar0*C2_PW + nb*4 + tid]     = __floats2half2_rn(d[nb][0], d[nb][1]);
        hst2[(ar0+8)*C2_PW + nb*4 + tid] = __floats2half2_rn(d[nb][2], d[nb][3]);
    }
    __syncthreads();
    {
        __half2* dst = (__half2*)&g_h2h[(size_t)rbase*HD];
        for (int e = t; e < 128*64; e += 256) {
            int r = e >> 6, j = e & 63;
            dst[e] = hst2[r*C2_PW + j];
        }
    }
    {
        int c2 = t & 63, rg = t >> 6;
        float s0 = 0.f, q0 = 0.f, s1 = 0.f, q1 = 0.f;
        for (int r = rg*32; r < rg*32 + 32; r++) {
            float2 f = __half22float2(hst2[r*C2_PW + c2]);
            s0 += f.x; q0 += f.x*f.x;
            s1 += f.y; q1 += f.y*f.y;
        }
        atomicAdd(&g_sum[HD + 2*c2],     s0);
        atomicAdd(&g_sumsq[HD + 2*c2],   q0);
        atomicAdd(&g_sum[HD + 2*c2+1],   s1);
        atomicAdd(&g_sumsq[HD + 2*c2+1], q1);
    }
    __threadfence();
    __syncthreads();
    if (t == 0) lastflag = (atomicAdd(&g_cnt[1], 1) == (int)gridDim.x - 1);
    __syncthreads();
    if (lastflag) bn_finalize(1, 128, invN, bn2g, bn2b, t);
}

/* ---------------- K5: conv3 via warp mma (W hi/lo) + pool + finalize --------
   FIXED: __syncthreads() between sc/sh staging and stage-A (was the R9/R11 bug) */
#define C3_AS 0
#define C3_WH 41600
#define C3_WL (41600 + 6272)
#define C3_H3 (41600 + 2*6272)
#define C3_SC (C3_H3 + 16000)
#define C3_SH (C3_SC + 512)
#define C3_RED (C3_SH + 512)
#define SMEM3 (C3_RED + 256)
__global__ void __launch_bounds__(192) k_conv3p(const float* __restrict__ w3,
                                                const float* __restrict__ bn3g,
                                                const float* __restrict__ bn3b,
                                                float invN) {
    extern __shared__ char smemraw[];
    __half* Wh = (__half*)(smemraw + C3_WH);
    __half* Wl = (__half*)(smemraw + C3_WL);
    float*  h3s = (float*)(smemraw + C3_H3);
    float*  sc = (float*)(smemraw + C3_SC);
    float*  sh = (float*)(smemraw + C3_SH);
    float*  red = (float*)(smemraw + C3_RED);
    __shared__ int lastflag;

    int t = threadIdx.x, blk = blockIdx.x;
    int lane = t & 31, w = t >> 5;
    int rbase = blk * 160;

    for (int e = t; e < 24*128; e += 192) {
        int n = e % 24, k = e / 24;
        float vv = w3[e];
        __half hi = __float2half(vv);
        Wh[n*130 + k] = hi;
        Wl[n*130 + k] = __float2half(vv - __half2float(hi));
    }
    if (t < 128) { sc[t] = g_scale[HD + t]; sh[t] = g_shift[HD + t]; }
    if (t < 48)  red[t] = 0.f;
    __syncthreads();   /* THE FIX: sc/sh must be visible before stage A reads them */
    /* stage A: h2 fp16 -> bn2+lrelu -> fp16 */
    {
        __half2* As2 = (__half2*)(smemraw + C3_AS);
        const __half2* hp = (const __half2*)g_h2h + (size_t)rbase*64;
        for (int e = t; e < 160*64; e += 192) {
            int r = e >> 6, kp = e & 63;
            float2 f = __half22float2(hp[(size_t)r*64 + kp]);
            int k0 = 2*kp;
            float v0 = fmaf(sc[k0],   f.x, sh[k0]);   v0 = (v0 > 0.f) ? v0 : 0.2f*v0;
            float v1 = fmaf(sc[k0+1], f.y, sh[k0+1]); v1 = (v1 > 0.f) ? v1 : 0.2f*v1;
            As2[r*65 + kp] = __floats2half2_rn(v0, v1);
        }
    }
    __syncthreads();

    const uint32_t* A32 = (const uint32_t*)(smemraw + C3_AS);
    const uint32_t* W32h = (const uint32_t*)(smemraw + C3_WH);
    const uint32_t* W32l = (const uint32_t*)(smemraw + C3_WL);
    int gid = lane >> 2, tid = lane & 3;
    int nb = w >> 1, mtb = (w & 1)*5;
    float d[5][4];
#pragma unroll
    for (int m = 0; m < 5; m++)
#pragma unroll
        for (int j = 0; j < 4; j++) d[m][j] = 0.f;

#pragma unroll
    for (int k0 = 0; k0 < 8; k0++) {
        int kc = k0*8 + tid;
        uint32_t bh0 = W32h[(nb*8+gid)*65 + kc];
        uint32_t bh1 = W32h[(nb*8+gid)*65 + kc + 4];
        uint32_t bl0 = W32l[(nb*8+gid)*65 + kc];
        uint32_t bl1 = W32l[(nb*8+gid)*65 + kc + 4];
#pragma unroll
        for (int m = 0; m < 5; m++) {
            int row = (mtb + m)*16 + gid;
            uint32_t a0 = A32[row*65 + kc];
            uint32_t a1 = A32[(row+8)*65 + kc];
            uint32_t a2 = A32[row*65 + kc + 4];
            uint32_t a3 = A32[(row+8)*65 + kc + 4];
            mma16816(d[m], a0, a1, a2, a3, bh0, bh1);
            mma16816(d[m], a0, a1, a2, a3, bl0, bl1);
        }
    }

    {
        int col = nb*8 + tid*2;
        float se = 0.f, qe = 0.f, so = 0.f, qo = 0.f;
#pragma unroll
        for (int m = 0; m < 5; m++) {
            int row = (mtb + m)*16 + gid;
            h3s[row*25 + col]       = d[m][0];
            h3s[row*25 + col+1]     = d[m][1];
            h3s[(row+8)*25 + col]   = d[m][2];
            h3s[(row+8)*25 + col+1] = d[m][3];
            se += d[m][0] + d[m][2]; qe += d[m][0]*d[m][0] + d[m][2]*d[m][2];
            so += d[m][1] + d[m][3]; qo += d[m][1]*d[m][1] + d[m][3]*d[m][3];
        }
        atomicAdd(&red[col], se);
        atomicAdd(&red[24 + col], qe);
        atomicAdd(&red[col+1], so);
        atomicAdd(&red[24 + col+1], qo);
    }
    __syncthreads();

    {
        int pl = t / 24, c2 = t % 24;
        float mx = -3.4e38f, mn = 3.4e38f;
#pragma unroll
        for (int kk = 0; kk < KNN; kk++) {
            float v = h3s[(pl*KNN + kk)*25 + c2];
            mx = fmaxf(mx, v); mn = fminf(mn, v);
        }
        int pt = blk*8 + pl;
        g_pmax[pt*24 + c2] = mx;
        g_pmin[pt*24 + c2] = mn;
    }
    if (t < 24) {
        atomicAdd(&g_sum[2*HD + t],   red[t]);
        atomicAdd(&g_sumsq[2*HD + t], red[24 + t]);
    }
    __threadfence();
    __syncthreads();
    if (t == 0) lastflag = (atomicAdd(&g_cnt[2], 1) == (int)gridDim.x - 1);
    __syncthreads();
    if (lastflag) bn_finalize(2, 24, invN, bn3g, bn3b, t);
}

/* ---------------- K6: ResNet-FC head: mma 3-term split for blk GEMMs -------- */
#define H_NET 0
#define H_AH  32768
#define H_AL  49408
#define H_WH  66048
#define H_WL  99328
#define H_CB  132608
#define H_PB  138752
#define H_FO  139520
#define SMEMH 140288
__global__ void __launch_bounds__(256) k_head(const float* __restrict__ p,
                       const float* __restrict__ fpw, const float* __restrict__ fpb,
                       const float* __restrict__ fcw, const float* __restrict__ fcb,
                       const float* __restrict__ b0w, const float* __restrict__ b0b,
                       const float* __restrict__ b1w, const float* __restrict__ b1b,
                       const float* __restrict__ fow, const float* __restrict__ fob,
                       float* __restrict__ out) {
    extern __shared__ char sm[];
    float*   net = (float*)(sm + H_NET);
    __half2* Ah2 = (__half2*)(sm + H_AH);
    __half2* Al2 = (__half2*)(sm + H_AL);
    __half*  WhH = (__half*)(sm + H_WH);
    __half*  WlH = (__half*)(sm + H_WL);
    float*   cb  = (float*)(sm + H_CB);
    float*   pb  = (float*)(sm + H_PB);
    float*   fo  = (float*)(sm + H_FO);

    int t = threadIdx.x, lane = t & 31, w = t >> 5;
    int gid = lane >> 2, tid = lane & 3;
    int mt = w & 3, nh = w >> 2;
    int row = mt*16 + gid;
    int base = blockIdx.x * 64;

    for (int e = t; e < 64*CD; e += 256) {
        int c2 = e % 24;
        float scv = g_scale[2*HD + c2], shv = g_shift[2*HD + c2];
        float v = (scv >= 0.f) ? g_pmax[base*24 + e] : g_pmin[base*24 + e];
        v = fmaf(scv, v, shv);
        cb[e] = (v > 0.f) ? v : 0.2f*v;
    }
    if (t < 192) pb[t] = p[base*3 + t];
    if (t < 128) fo[t] = fow[t];
    __syncthreads();

    int cg  = (t & 31) * 4;
    int row0 = (t >> 5) * 8;

    { /* net = p @ fc_p_w + b */
        float4 w0 = *(const float4*)&fpw[0*HD + cg];
        float4 w1 = *(const float4*)&fpw[1*HD + cg];
        float4 w2 = *(const float4*)&fpw[2*HD + cg];
        float4 b4 = *(const float4*)&fpb[cg];
#pragma unroll
        for (int rr = 0; rr < 8; rr++) {
            int rw = row0 + rr;
            float p0 = pb[rw*3+0], p1 = pb[rw*3+1], p2 = pb[rw*3+2];
            float4 v;
            v.x = fmaf(p0,w0.x, fmaf(p1,w1.x, fmaf(p2,w2.x, b4.x)));
            v.y = fmaf(p0,w0.y, fmaf(p1,w1.y, fmaf(p2,w2.y, b4.y)));
            v.z = fmaf(p0,w0.z, fmaf(p1,w1.z, fmaf(p2,w2.z, b4.z)));
            v.w = fmaf(p0,w0.w, fmaf(p1,w1.w, fmaf(p2,w2.w, b4.w)));
            *(float4*)&net[rw*128 + cg] = v;
        }
    }
    __syncthreads();

    const uint32_t* A32h = (const uint32_t*)(sm + H_AH);
    const uint32_t* A32l = (const uint32_t*)(sm + H_AL);
    const uint32_t* W32h = (const uint32_t*)(sm + H_WH);
    const uint32_t* W32l = (const uint32_t*)(sm + H_WL);

    for (int i = 0; i < NB; i++) {
        { /* net += c @ fc_c[i] + b ; split relu(net) -> Ah/Al */
            float4 b4 = *(const float4*)&fcb[i*HD + cg];
            ull acc2[8][4];
#pragma unroll
            for (int rr = 0; rr < 8; rr++) {
                float4 v = *(const float4*)&net[(row0+rr)*128 + cg];
                acc2[rr][0] = pack2(v.x + b4.x, 0.f);
                acc2[rr][1] = pack2(v.y + b4.y, 0.f);
                acc2[rr][2] = pack2(v.z + b4.z, 0.f);
                acc2[rr][3] = pack2(v.w + b4.w, 0.f);
            }
#pragma unroll 2
            for (int k = 0; k < CD; k += 2) {
                float4 wa = __ldg((const float4*)&fcw[(i*CD + k)*HD + cg]);
                float4 wb = __ldg((const float4*)&fcw[(i*CD + k + 1)*HD + cg]);
                ull wx = pack2(wa.x, wb.x), wy = pack2(wa.y, wb.y);
                ull wz = pack2(wa.z, wb.z), ww = pack2(wa.w, wb.w);
#pragma unroll
                for (int rr = 0; rr < 8; rr++) {
                    ull a = *(const ull*)&cb[(row0+rr)*24 + k];
                    acc2[rr][0] = ffma2(a, wx, acc2[rr][0]);
                    acc2[rr][1] = ffma2(a, wy, acc2[rr][1]);
                    acc2[rr][2] = ffma2(a, wz, acc2[rr][2]);
                    acc2[rr][3] = ffma2(a, ww, acc2[rr][3]);
                }
            }
#pragma unroll
            for (int rr = 0; rr < 8; rr++) {
                int rw = row0 + rr;
                float2 f0 = unpack2(acc2[rr][0]), f1 = unpack2(acc2[rr][1]);
                float2 f2 = unpack2(acc2[rr][2]), f3 = unpack2(acc2[rr][3]);
                float4 v; v.x = f0.x+f0.y; v.y = f1.x+f1.y; v.z = f2.x+f2.y; v.w = f3.x+f3.y;
                *(float4*)&net[rw*128 + cg] = v;
                float ax = fmaxf(v.x,0.f), ay = fmaxf(v.y,0.f);
                float az = fmaxf(v.z,0.f), aw = fmaxf(v.w,0.f);
                __half hx = __float2half(ax), hy = __float2half(ay);
                __half hz = __float2half(az), hw = __float2half(aw);
                Ah2[rw*65 + (cg>>1)]     = __halves2half2(hx, hy);
                Ah2[rw*65 + (cg>>1) + 1] = __halves2half2(hz, hw);
                Al2[rw*65 + (cg>>1)]     = __halves2half2(__float2half(ax - __half2float(hx)),
                                                          __float2half(ay - __half2float(hy)));
                Al2[rw*65 + (cg>>1) + 1] = __halves2half2(__float2half(az - __half2float(hz)),
                                                          __float2half(aw - __half2float(hw)));
            }
        }
        { /* stage W0 hi/lo */
            const float* wb = b0w + (size_t)i*HD*HD;
            for (int e = t; e < HD*HD; e += 256) {
                float vv = wb[e];
                int k = e >> 7, n = e & 127;
                __half hi = __float2half(vv);
                WhH[n*130 + k] = hi;
                WlH[n*130 + k] = __float2half(vv - __half2float(hi));
            }
        }
        __syncthreads();
        /* mma blk0 */
        float d0[8][4];
#pragma unroll
        for (int nb = 0; nb < 8; nb++)
#pragma unroll
            for (int j = 0; j < 4; j++) d0[nb][j] = 0.f;
#pragma unroll
        for (int k0 = 0; k0 < 8; k0++) {
            int kc = k0*8 + tid;
            uint32_t ah0 = A32h[row*65 + kc],     ah1 = A32h[(row+8)*65 + kc];
            uint32_t ah2 = A32h[row*65 + kc + 4], ah3 = A32h[(row+8)*65 + kc + 4];
            uint32_t al0 = A32l[row*65 + kc],     al1 = A32l[(row+8)*65 + kc];
            uint32_t al2 = A32l[row*65 + kc + 4], al3 = A32l[(row+8)*65 + kc + 4];
#pragma unroll
            for (int nb = 0; nb < 8; nb++) {
                int nr = nh*64 + nb*8 + gid;
                uint32_t bh0 = W32h[nr*65 + kc], bh1 = W32h[nr*65 + kc + 4];
                uint32_t bl0 = W32l[nr*65 + kc], bl1 = W32l[nr*65 + kc + 4];
                mma16816(d0[nb], ah0, ah1, ah2, ah3, bh0, bh1);
                mma16816(d0[nb], ah0, ah1, ah2, ah3, bl0, bl1);
                mma16816(d0[nb], al0, al1, al2, al3, bh0, bh1);
            }
        }
        __syncthreads();
        /* epi0: hh = relu(d0+b0b) -> Ah/Al ; stage W1 */
#pragma unroll
        for (int nb = 0; nb < 8; nb++) {
            int col = nh*64 + nb*8 + tid*2;
            float bb0 = __ldg(&b0b[i*HD + col]);
            float bb1 = __ldg(&b0b[i*HD + col + 1]);
            float v0 = fmaxf(d0[nb][0] + bb0, 0.f);
            float v1 = fmaxf(d0[nb][1] + bb1, 0.f);
            float v2 = fmaxf(d0[nb][2] + bb0, 0.f);
            float v3 = fmaxf(d0[nb][3] + bb1, 0.f);
            __half h0 = __float2half(v0), h1 = __float2half(v1);
            __half h2 = __float2half(v2), h3 = __float2half(v3);
            Ah2[row*65 + (col>>1)]     = __halves2half2(h0, h1);
            Ah2[(row+8)*65 + (col>>1)] = __halves2half2(h2, h3);
            Al2[row*65 + (col>>1)]     = __halves2half2(__float2half(v0 - __half2float(h0)),
                                                        __float2half(v1 - __half2float(h1)));
            Al2[(row+8)*65 + (col>>1)] = __halves2half2(__float2half(v2 - __half2float(h2)),
                                                        __float2half(v3 - __half2float(h3)));
        }
        {
            const float* wb = b1w + (size_t)i*HD*HD;
            for (int e = t; e < HD*HD; e += 256) {
                float vv = wb[e];
                int k = e >> 7, n = e & 127;
                __half hi = __float2half(vv);
                WhH[n*130 + k] = hi;
                WlH[n*130 + k] = __float2half(vv - __half2float(hi));
            }
        }
        __syncthreads();
        /* mma blk1 */
        float d1[8][4];
#pragma unroll
        for (int nb = 0; nb < 8; nb++)
#pragma unroll
            for (int j = 0; j < 4; j++) d1[nb][j] = 0.f;
#pragma unroll
        for (int k0 = 0; k0 < 8; k0++) {
            int kc = k0*8 + tid;
            uint32_t ah0 = A32h[row*65 + kc],     ah1 = A32h[(row+8)*65 + kc];
            uint32_t ah2 = A32h[row*65 + kc + 4], ah3 = A32h[(row+8)*65 + kc + 4];
            uint32_t al0 = A32l[row*65 + kc],     al1 = A32l[(row+8)*65 + kc];
            uint32_t al2 = A32l[row*65 + kc + 4], al3 = A32l[(row+8)*65 + kc + 4];
#pragma unroll
            for (int nb = 0; nb < 8; nb++) {
                int nr = nh*64 + nb*8 + gid;
                uint32_t bh0 = W32h[nr*65 + kc], bh1 = W32h[nr*65 + kc + 4];
                uint32_t bl0 = W32l[nr*65 + kc], bl1 = W32l[nr*65 + kc + 4];
                mma16816(d1[nb], ah0, ah1, ah2, ah3, bh0, bh1);
                mma16816(d1[nb], ah0, ah1, ah2, ah3, bl0, bl1);
                mma16816(d1[nb], al0, al1, al2, al3, bh0, bh1);
            }
        }
        /* epi1: net += d1 + b1b (net disjoint from A/W regions) */
#pragma unroll
        for (int nb = 0; nb < 8; nb++) {
            int col = nh*64 + nb*8 + tid*2;
            float bb0 = __ldg(&b1b[i*HD + col]);
            float bb1 = __ldg(&b1b[i*HD + col + 1]);
            net[row*128 + col]         += d1[nb][0] + bb0;
            net[row*128 + col + 1]     += d1[nb][1] + bb1;
            net[(row+8)*128 + col]     += d1[nb][2] + bb0;
            net[(row+8)*128 + col + 1] += d1[nb][3] + bb1;
        }
        __syncthreads();
    }

    if (t < 64) {
        float s = fob[0];
        for (int c2 = 0; c2 < HD; c2++)
            s = fmaf(fmaxf(net[t*128 + c2], 0.f), fo[c2], s);
        out[base + t] = s;
    }
}

/* ---------------- launch ---------------- */
extern "C" void kernel_launch(void* const* d_in, const int* in_sizes, int n_in,
                              void* d_out, int out_size) {
    (void)in_sizes; (void)n_in; (void)out_size;
    const float* p     = (const float*)d_in[0];
    const float* pc    = (const float*)d_in[1];
    const float* feat  = (const float*)d_in[2];
    const float* w1    = (const float*)d_in[3];
    const float* bn1g  = (const float*)d_in[4];
    const float* bn1b  = (const float*)d_in[5];
    const float* w2    = (const float*)d_in[6];
    const float* bn2g  = (const float*)d_in[7];
    const float* bn2b  = (const float*)d_in[8];
    const float* w3    = (const float*)d_in[9];
    const float* bn3g  = (const float*)d_in[10];
    const float* bn3b  = (const float*)d_in[11];
    const float* fpw   = (const float*)d_in[12];
    const float* fpb   = (const float*)d_in[13];
    const float* fcw   = (const float*)d_in[14];
    const float* fcb   = (const float*)d_in[15];
    const float* b0w   = (const float*)d_in[16];
    const float* b0b   = (const float*)d_in[17];
    const float* b1w   = (const float*)d_in[18];
    const float* b1b   = (const float*)d_in[19];
    const float* fow   = (const float*)d_in[20];
    const float* fob   = (const float*)d_in[21];
    float* out = (float*)d_out;

    cudaFuncSetAttribute(k_conv2,  cudaFuncAttributeMaxDynamicSharedMemorySize, C2_SMEM);
    cudaFuncSetAttribute(k_conv3p, cudaFuncAttributeMaxDynamicSharedMemorySize, SMEM3);
    cudaFuncSetAttribute(k_head,   cudaFuncAttributeMaxDynamicSharedMemorySize, SMEMH);

    float invN = 1.0f / (float)NROWS;

    k_knn<<<dim3(NX/256, BSZ), 256>>>(p, pc);
    k_preUVW<<<768, 128>>>(p, pc, feat, w1, w2);
    k_stats1<<<NROWS/512, 256>>>(bn1g, bn1b, invN);
    k_conv2<<<NROWS/128, 256, C2_SMEM>>>(bn2g, bn2b, invN);
    k_conv3p<<<NROWS/160, 192, SMEM3>>>(w3, bn3g, bn3b, invN);
    k_head<<<NPTS/64, 256, SMEMH>>>(p, fpw, fpb, fcw, fcb,
                                    b0w, b0b, b1w, b1b, fow, fob, out);
}